// round 14
// baseline (speedup 1.0000x reference)
#include <cuda_runtime.h>
#include <cuda_fp16.h>

#define NUM_C 32
#define MAX_H 262144   // 64^3 nodes at depth 6
#define MAX_G 64
#define MAX_GG (MAX_G + 1)   // base-cell coord range [-1, G-1] -> 65 values

// 16 MB: transposed fp16 feature table, 64B rows, channel-PERMUTED within row:
//   16B chunk j, half2 slot u holds channels (2j+8u, 2j+8u+1)
__device__ __align__(16) __half g_feat_h[(size_t)MAX_H * NUM_C];
// 8.8 MB packed cell table: 8 corner indices per base cell, 32B rows.
__device__ __align__(16) int g_cell[(size_t)MAX_GG * MAX_GG * MAX_GG * 8];

// ---------------------------------------------------------------------------
// Kernel 1 (fused prep): transpose+convert + packed cell table.
// PDL trigger is the LAST statement: every thread's writes precede its
// trigger, so the dependent gather (after cudaGridDependencySynchronize)
// sees all prep output. Overlap = secondary launch latency + prologue
// hidden inside prep's drain.
// ---------------------------------------------------------------------------
__global__ void __launch_bounds__(256)
prep_kernel(const float* __restrict__ data, const int* __restrict__ lut,
            int H, int G, int nTrans, int nbAxis)
{
    __shared__ float smbuf[32 * 260];   // 33.3 KB, reused by both branches
    const int tid = threadIdx.x;

    if ((int)blockIdx.x < nTrans) {
        // ---- transpose + fp16 convert, 32c x 256h tile ----
        float (*tile)[260] = reinterpret_cast<float (*)[260]>(smbuf);
        const int hbase = blockIdx.x * 256;

        if (hbase + 256 <= H) {
#pragma unroll
            for (int i = 0; i < 8; ++i) {
                const int flat = i * 256 + tid;     // 0..2047
                const int c    = flat >> 6;         // channel 0..31
                const int seg  = flat & 63;         // float4 slot 0..63
                const float4 v = *reinterpret_cast<const float4*>(
                    &data[(size_t)c * H + hbase + 4 * seg]);
                tile[c][4 * seg]     = v.x;
                tile[c][4 * seg + 1] = v.y;
                tile[c][4 * seg + 2] = v.z;
                tile[c][4 * seg + 3] = v.w;
            }
        } else {
            for (int flat = tid; flat < 32 * 256; flat += 256) {
                const int c = flat >> 8;
                const int hh = flat & 255;
                if (hbase + hh < H)
                    tile[c][hh] = data[(size_t)c * H + hbase + hh];
            }
        }
        __syncthreads();

        // store: one full 16B chunk per task (4 half2, STG.128)
        uint4* feat16 = reinterpret_cast<uint4*>(g_feat_h);
#pragma unroll
        for (int r = 0; r < 4; ++r) {
            const int e   = r * 256 + tid;    // 0..1023
            const int row = e >> 2;           // h within tile 0..255
            const int s4  = e & 3;            // chunk id 0..3
            const int h   = hbase + row;
            if (h < H) {
                uint4 outv;
                unsigned* ov = reinterpret_cast<unsigned*>(&outv);
#pragma unroll
                for (int b = 0; b < 4; ++b) {
                    const int c0 = (s4 << 1) | (b << 3);
                    const __half2 hv =
                        __floats2half2_rn(tile[c0][row], tile[c0 | 1][row]);
                    ov[b] = *reinterpret_cast<const unsigned*>(&hv);
                }
                feat16[(size_t)h * 4 + s4] = outv;
            }
        }
    } else {
        // ---- cell table: block = 8x8x8 cells, smem lut tile 9x9x9 ----
        int* s = reinterpret_cast<int*>(smbuf);   // s[i*81 + jj*9 + kk]
        const int GG = G + 1;
        const int b  = blockIdx.x - nTrans;
        const int Zb = b % nbAxis;
        const int Yb = (b / nbAxis) % nbAxis;
        const int Xb = b / (nbAxis * nbAxis);
        const int c0x = Xb * 8, c0y = Yb * 8, c0z = Zb * 8;

        for (int t = tid; t < 729; t += 256) {
            const int i  = t / 81;
            const int jj = (t / 9) % 9;
            const int kk = t % 9;
            const int vx = c0x - 1 + i;
            const int vy = c0y - 1 + jj;
            const int vz = c0z - 1 + kk;
            int val = -1;
            if (((unsigned)vx < (unsigned)G) & ((unsigned)vy < (unsigned)G) &
                ((unsigned)vz < (unsigned)G))
                val = __ldg(&lut[((size_t)vx * G + vy) * G + vz]);
            s[t] = val;
        }
        __syncthreads();

        for (int t = tid; t < 512; t += 256) {
            const int lx = t >> 6;
            const int ly = (t >> 3) & 7;
            const int lz = t & 7;
            const int cx = c0x + lx;
            const int cy = c0y + ly;
            const int cz = c0z + lz;
            if ((cx < GG) & (cy < GG) & (cz < GG)) {
                const int base = lx * 81 + ly * 9 + lz;
                int v[8];
#pragma unroll
                for (int k = 0; k < 8; ++k) {
                    const int kx = (k >> 2) & 1, ky = (k >> 1) & 1, kz = k & 1;
                    v[k] = s[base + kx * 81 + ky * 9 + kz];
                }
                const int cid = (cx * GG + cy) * GG + cz;
                int4* dst = reinterpret_cast<int4*>(&g_cell[(size_t)cid * 8]);
                dst[0] = make_int4(v[0], v[1], v[2], v[3]);
                dst[1] = make_int4(v[4], v[5], v[6], v[7]);
            }
        }
    }

#if __CUDA_ARCH__ >= 900
    // All of this thread's global writes are program-ordered BEFORE the
    // trigger -> visible to the dependent grid after its sync.
    cudaTriggerProgrammaticLaunchCompletion();
#endif
}

// ---------------------------------------------------------------------------
// Kernel 2: cooperative gather (LTS-cap bound). PDL: prologue (pts+geometry)
// runs before cudaGridDependencySynchronize(); cell/feat reads after.
// ---------------------------------------------------------------------------
__global__ void __launch_bounds__(256)
octree_trilinear_coop4(const float4* __restrict__ pts,
                       float*        __restrict__ out,
                       int N, int G)
{
    __shared__ float sm[32][132];    // [channel][point 0..127], stride 132

    const int tid    = threadIdx.x;
    const int warpId = tid >> 5;
    const int lane   = tid & 31;
    const int g      = lane >> 2;    // point-in-warp 0..7
    const int j      = lane & 3;     // chunk id 0..3

    const int n0   = blockIdx.x * 128;
    const int pL0  = warpId * 8 + g;          // tile-0 point 0..63
    const int pL1  = pL0 + 64;                // tile-1 point 64..127
    const int GG   = G + 1;

    const int pc0 = min(n0 + pL0, N - 1);
    const int pc1 = min(n0 + pL1, N - 1);

    const float4 q0 = __ldcs(&pts[pc0]);
    const float4 q1 = __ldcs(&pts[pc1]);

#define GEOM(q, fx, fy, fz, cid)                                          \
    float fx, fy, fz; int cid;                                            \
    do {                                                                  \
        const float xf = (q).x - 0.5f, yf = (q).y - 0.5f, zf = (q).z - 0.5f; \
        const float xi = floorf(xf), yi = floorf(yf), zi = floorf(zf);    \
        fx = xf - xi; fy = yf - yi; fz = zf - zi;                         \
        const int ix = min(max((int)xi, -1), G - 1);                      \
        const int iy = min(max((int)yi, -1), G - 1);                      \
        const int iz = min(max((int)zi, -1), G - 1);                      \
        cid = ((ix + 1) * GG + (iy + 1)) * GG + (iz + 1);                 \
    } while (0)

    GEOM(q0, fx0, fy0, fz0, cid0);
    GEOM(q1, fx1, fy1, fz1, cid1);
#undef GEOM

#if __CUDA_ARCH__ >= 900
    cudaGridDependencySynchronize();   // prep outputs fully visible after this
#endif

    const int4* __restrict__ cell4 = reinterpret_cast<const int4*>(g_cell);
    const int4 lo0 = __ldg(&cell4[(size_t)cid0 * 2]);
    const int4 hi0 = __ldg(&cell4[(size_t)cid0 * 2 + 1]);
    const int4 lo1 = __ldg(&cell4[(size_t)cid1 * 2]);
    const int4 hi1 = __ldg(&cell4[(size_t)cid1 * 2 + 1]);

    const uint4* __restrict__ feat16 = reinterpret_cast<const uint4*>(g_feat_h);

#define WEIGHTS(lo, hi, fx, fy, fz, wk, rk, wsum)                         \
    float wk[8]; int rk[8]; float wsum;                                   \
    do {                                                                  \
        rk[0] = (lo).x; rk[1] = (lo).y; rk[2] = (lo).z; rk[3] = (lo).w;   \
        rk[4] = (hi).x; rk[5] = (hi).y; rk[6] = (hi).z; rk[7] = (hi).w;   \
        const float wx0 = 1.0f - (fx), wy0 = 1.0f - (fy), wz0 = 1.0f - (fz); \
        wsum = 0.0f;                                                      \
        _Pragma("unroll")                                                 \
        for (int k = 0; k < 8; ++k) {                                     \
            const float w = ((k & 4) ? (fx) : wx0) *                      \
                            ((k & 2) ? (fy) : wy0) *                      \
                            ((k & 1) ? (fz) : wz0);                       \
            wk[k] = (rk[k] >= 0) ? w : 0.0f;                              \
            rk[k] = max(rk[k], 0);                                        \
            wsum += wk[k];                                                \
        }                                                                 \
    } while (0)

#define CONSUME(v, w, acc)                                                \
    do {                                                                  \
        const __half2* hp = reinterpret_cast<const __half2*>(&(v));       \
        _Pragma("unroll")                                                 \
        for (int u = 0; u < 4; ++u) {                                     \
            const float2 f = __half22float2(hp[u]);                       \
            acc[u].x = fmaf((w), f.x, acc[u].x);                          \
            acc[u].y = fmaf((w), f.y, acc[u].y);                          \
        }                                                                 \
    } while (0)

#define RUN_TILE(lo, hi, fx, fy, fz, pL)                                  \
    do {                                                                  \
        WEIGHTS(lo, hi, fx, fy, fz, wk, rk, wsum);                        \
        float2 acc[4];                                                    \
        _Pragma("unroll")                                                 \
        for (int u = 0; u < 4; ++u) acc[u] = make_float2(0.f, 0.f);       \
        uint4 v0 = __ldg(&feat16[(size_t)rk[0] * 4 + j]);                 \
        uint4 v1 = __ldg(&feat16[(size_t)rk[1] * 4 + j]);                 \
        uint4 v2 = __ldg(&feat16[(size_t)rk[2] * 4 + j]);                 \
        uint4 v3 = __ldg(&feat16[(size_t)rk[3] * 4 + j]);                 \
        uint4 v4 = __ldg(&feat16[(size_t)rk[4] * 4 + j]); CONSUME(v0, wk[0], acc); \
        uint4 v5 = __ldg(&feat16[(size_t)rk[5] * 4 + j]); CONSUME(v1, wk[1], acc); \
        uint4 v6 = __ldg(&feat16[(size_t)rk[6] * 4 + j]); CONSUME(v2, wk[2], acc); \
        uint4 v7 = __ldg(&feat16[(size_t)rk[7] * 4 + j]); CONSUME(v3, wk[3], acc); \
        CONSUME(v4, wk[4], acc);                                          \
        CONSUME(v5, wk[5], acc);                                          \
        CONSUME(v6, wk[6], acc);                                          \
        CONSUME(v7, wk[7], acc);                                          \
        const float inv = 1.0f / (wsum + 1e-10f);                         \
        _Pragma("unroll")                                                 \
        for (int u = 0; u < 4; ++u) {                                     \
            sm[2 * j + 8 * u][pL]     = acc[u].x * inv;                   \
            sm[2 * j + 8 * u + 1][pL] = acc[u].y * inv;                   \
        }                                                                 \
    } while (0)

    RUN_TILE(lo0, hi0, fx0, fy0, fz0, pL0);
    RUN_TILE(lo1, hi1, fx1, fy1, fz1, pL1);
#undef RUN_TILE
#undef WEIGHTS
#undef CONSUME

    __syncthreads();

    if ((n0 + 128 <= N) && ((N & 3) == 0)) {
#pragma unroll
        for (int r = 0; r < 4; ++r) {
            const int e = r * 256 + tid;      // 0..1023
            const int c = e >> 5;             // channel 0..31
            const int s = e & 31;             // float4 slot 0..31
            const float4 val = *reinterpret_cast<const float4*>(&sm[c][4 * s]);
            __stcs(reinterpret_cast<float4*>(&out[(size_t)c * N + n0 + 4 * s]), val);
        }
    } else {
#pragma unroll
        for (int r = 0; r < 16; ++r) {
            const int e = r * 256 + tid;      // 0..4095
            const int c = e >> 7;             // channel
            const int i = e & 127;            // point-in-block
            if (n0 + i < N)
                out[(size_t)c * N + (n0 + i)] = sm[c][i];
        }
    }
}

// ---------------------------------------------------------------------------
// Launch. Inputs: data (f32), pts (f32), lut (i32), depth.
// ---------------------------------------------------------------------------
extern "C" void kernel_launch(void* const* d_in, const int* in_sizes, int n_in,
                              void* d_out, int out_size)
{
    const float* data = (const float*)d_in[0];
    const float* pts  = (const float*)d_in[1];
    const int*   lut  = (const int*)d_in[2];
    float*       out  = (float*)d_out;

    int G = 1;
    while (G * G * G < in_sizes[2]) G <<= 1;
    const int H = in_sizes[0] / NUM_C;
    const int N = in_sizes[1] / 4;

    {
        const int GG = G + 1;
        const int nbAxis = (GG + 7) / 8;
        const int nTrans = (H + 255) / 256;
        const int nBuild = nbAxis * nbAxis * nbAxis;
        prep_kernel<<<nTrans + nBuild, 256>>>(data, lut, H, G, nTrans, nbAxis);
    }
    {
        const int blocks = (N + 127) / 128;   // 128 points per 256-thread block

        cudaLaunchConfig_t cfg = {};
        cfg.gridDim  = dim3(blocks, 1, 1);
        cfg.blockDim = dim3(256, 1, 1);
        cfg.dynamicSmemBytes = 0;
        cfg.stream = 0;
        cudaLaunchAttribute attrs[1];
        attrs[0].id = cudaLaunchAttributeProgrammaticStreamSerialization;
        attrs[0].val.programmaticStreamSerializationAllowed = 1;
        cfg.attrs = attrs;
        cfg.numAttrs = 1;

        cudaError_t e = cudaLaunchKernelEx(&cfg, octree_trilinear_coop4,
                                           (const float4*)pts, out, N, G);
        if (e != cudaSuccess) {
            (void)cudaGetLastError();   // clear, then plain launch
            octree_trilinear_coop4<<<blocks, 256>>>(
                (const float4*)pts, out, N, G);
        }
    }
}